// round 3
// baseline (speedup 1.0000x reference)
#include <cuda_runtime.h>
#include <math_constants.h>
#include <cstdint>

// Problem: votes (16,6,6,3,3,32,32,4,4); EM routing, 2 iterations.
#define NPOS   576            // B*H*W
#define KHW    9              // KH*KW
#define II     32
#define OO     32
#define KDIM   (KHW*II)       // 288
#define PERPOS (KDIM*512)     // 147456 floats per position
#define EPSC   1e-7f
#define INVT1  0.0005f        // 0.01*(1-0.95^1)
#define INVT2  0.00142625f    // 0.01*(1-0.95^3)

#define CL     8              // CTAs per cluster (per position)
#define ILQ    4              // input capsules per CTA
#define KL     (KHW*ILQ)      // 36 local k slabs per CTA

// ---- smem layout (floats) ----
#define OFF_V      0                       // 36*512 = 18432
#define OFF_R1     (OFF_V + KL*512)        // 288
#define OFF_A8     (OFF_R1 + KDIM)         // 288
#define OFF_Q2     (OFF_A8 + KDIM)         // 512
#define OFF_MQ1    (OFF_Q2 + 512)          // 512
#define OFF_BASE   (OFF_MQ1 + 512)         // 32
#define OFF_LOGDEN (OFF_BASE + 32)         // 4
#define OFF_S1     (OFF_LOGDEN + 4)        // 4
#define OFF_PA     (OFF_S1 + 4)            // 1024 (pass A partials: av, av2)
#define OFF_PC     (OFF_PA + 1024)         // 1536 (pass C partials: cr, crv, crv2)
#define OFF_LN     (OFF_PC + 1536)         // 36*32 = 1152
#define SMEM_FLOATS (OFF_LN + KL*OO)
#define SMEM_BYTES  (SMEM_FLOATS * 4)      // 95136 B -> 2 CTAs/SM

extern __shared__ float smem[];

__device__ __forceinline__ uint32_t smem_u32(const void* p) {
    uint32_t r;
    asm("{ .reg .u64 t; cvta.to.shared.u64 t, %1; cvt.u32.u64 %0, t; }"
        : "=r"(r) : "l"(p));
    return r;
}
__device__ __forceinline__ uint32_t mapa_rank(uint32_t addr, uint32_t rank) {
    uint32_t r;
    asm("mapa.shared::cluster.u32 %0, %1, %2;" : "=r"(r) : "r"(addr), "r"(rank));
    return r;
}
__device__ __forceinline__ float ld_dsmem(uint32_t addr) {
    float v;
    asm volatile("ld.shared::cluster.f32 %0, [%1];" : "=f"(v) : "r"(addr));
    return v;
}
__device__ __forceinline__ void cluster_sync() {
    asm volatile("barrier.cluster.arrive.aligned;" ::: "memory");
    asm volatile("barrier.cluster.wait.aligned;"   ::: "memory");
}
__device__ __forceinline__ uint32_t ctarank() {
    uint32_t r;
    asm("mov.u32 %0, %%cluster_ctarank;" : "=r"(r));
    return r;
}

__global__ __launch_bounds__(512, 2) __cluster_dims__(CL, 1, 1)
void em_routing_kernel(const float* __restrict__ votes,
                       const float* __restrict__ activ,
                       const float* __restrict__ beta_a,
                       const float* __restrict__ beta_u,
                       float* __restrict__ out)
{
    float* s_V      = smem + OFF_V;
    float* s_R1     = smem + OFF_R1;
    float* s_a8     = smem + OFF_A8;
    float* s_q2     = smem + OFF_Q2;
    float* s_mq1    = smem + OFF_MQ1;
    float* s_base   = smem + OFF_BASE;
    float* s_logden = smem + OFF_LOGDEN;
    float* s_S1     = smem + OFF_S1;
    float* s_pA     = smem + OFF_PA;
    float* s_pC     = smem + OFF_PC;
    float* s_ln     = smem + OFF_LN;

    const int t   = threadIdx.x;          // 0..511
    const int q   = (int)ctarank();       // 0..7, owns i in [4q, 4q+4)
    const int pos = blockIdx.x / CL;
    const int c   = t;                    // column o*16+aa
    const int o   = c >> 4;
    const float* __restrict__ V  = votes + (int64_t)pos * PERPOS;
    const float* __restrict__ Ai = activ + pos * KDIM;

    // ---- prologue: full R1 / a8 tables (need all 288 for S1) ----
    if (t < KDIM) {
        float a = Ai[t];
        s_a8[t] = 0.8f * a;
        s_R1[t] = (0.8f * a + 0.2f) * (1.0f / 32.0f);
    }
    __syncthreads();
    if (t < 32) {
        float s = 0.f;
        #pragma unroll
        for (int k = t; k < KDIM; k += 32) s += s_R1[k];
        #pragma unroll
        for (int off = 16; off; off >>= 1) s += __shfl_xor_sync(0xffffffffu, s, off);
        if (t == 0) s_S1[0] = s;
    }

    // ---- Pass A: stream own 36 slabs gmem -> SMEM, accumulate R1*V, R1*V^2 ----
    float av = 0.f, av2 = 0.f;
    {
        const float* gbase = V + (size_t)(4 * q) * 512 + c;
        #pragma unroll 12
        for (int kl = 0; kl < KL; ++kl) {
            const int gk = (kl >> 2) * 32 + (kl & 3);   // khw*32 + il (rel. to 4q)
            float v = gbase[(size_t)gk * 512];
            s_V[kl * 512 + c] = v;
            float r  = s_R1[gk + 4 * q];
            float rv = r * v;
            av  += rv;
            av2  = fmaf(rv, v, av2);
        }
        s_pA[c] = av;
        s_pA[512 + c] = av2;
    }
    __syncthreads();
    cluster_sync();

    // ---- reduce pass A across 8 CTAs; CTA q owns columns [64q, 64q+64) ----
    if (t < 64) {
        const int cp = 64 * q + t;
        const int op = cp >> 4, ap = cp & 15;
        const uint32_t pa = smem_u32(s_pA) + cp * 4;
        float sa = 0.f, sa2 = 0.f;
        #pragma unroll
        for (int r = 0; r < CL; ++r) {
            uint32_t ra = mapa_rank(pa, r);
            sa  += ld_dsmem(ra);
            sa2 += ld_dsmem(ra + 2048);
        }
        const float S1    = s_S1[0];
        const float invS1 = 1.0f / (S1 + EPSC);
        const float mu1   = sa * invS1;
        const float sig1  = fmaf(mu1 * mu1, S1, fmaf(-2.0f * mu1, sa, sa2)) * invS1;
        const float i2s1  = 0.5f / sig1;             // 1/(2*sigma^2), no eps (ref)
        const float q1    = mu1 * i2s1;
        s_q2 [cp] = i2s1;
        s_mq1[cp] = -2.0f * q1;

        float Co   = mu1 * q1;                                       // mu^2/(2s)
        float c0   = __logf(fmaf(2.0f * CUDART_PI_F, sig1, EPSC));
        float cost = (beta_u[op] - 0.5f * __logf(sig1 + EPSC)) * S1;
        #pragma unroll
        for (int off = 8; off; off >>= 1) {
            Co   += __shfl_xor_sync(0xffffffffu, Co,   off);
            c0   += __shfl_xor_sync(0xffffffffu, c0,   off);
            cost += __shfl_xor_sync(0xffffffffu, cost, off);
        }
        if (ap == 0) {
            float arg = INVT1 * (beta_a[op] - cost);
            float aj  = 1.0f / (1.0f + __expf(-arg));
            s_base[op] = __logf(aj + EPSC) - c0 - Co;
        }
    }
    __syncthreads();
    cluster_sync();

    // ---- gather full mu/sigma tables from owner CTAs ----
    {
        const int ro = c >> 6;
        if (ro != q) {
            s_q2 [c] = ld_dsmem(mapa_rank(smem_u32(s_q2)  + c * 4, ro));
            s_mq1[c] = ld_dsmem(mapa_rank(smem_u32(s_mq1) + c * 4, ro));
        }
        if (t < 32) {
            const int rb = t >> 2;
            if (rb != q)
                s_base[t] = ld_dsmem(mapa_rank(smem_u32(s_base) + t * 4, rb));
        }
    }
    __syncthreads();

    // ---- Pass B (E-step): log_num[kl][o] from SMEM V ----
    {
        const float q2c = s_q2[c], mqc = s_mq1[c];
        const float baseo = s_base[o];
        #pragma unroll 12
        for (int kl = 0; kl < KL; ++kl) {
            float v = s_V[kl * 512 + c];
            float term = v * fmaf(v, q2c, mqc);      // v^2*q2 + v*mq1
            #pragma unroll
            for (int off = 8; off; off >>= 1)
                term += __shfl_xor_sync(0xffffffffu, term, off);
            if ((c & 15) == 0) s_ln[kl * OO + o] = baseo - term;
        }
    }
    __syncthreads();

    // ---- logsumexp over (khw, o) per owned i (fully CTA-local) ----
    if (t < 128) {
        const int il = t >> 5, lane = t & 31;
        float x[KHW];
        float m = -CUDART_INF_F;
        #pragma unroll
        for (int kk = 0; kk < KHW; ++kk) {
            x[kk] = s_ln[(kk * ILQ + il) * OO + lane];
            m = fmaxf(m, x[kk]);
        }
        #pragma unroll
        for (int off = 16; off; off >>= 1)
            m = fmaxf(m, __shfl_xor_sync(0xffffffffu, m, off));
        float s = 0.f;
        #pragma unroll
        for (int kk = 0; kk < KHW; ++kk) s += __expf(x[kk] - m);
        #pragma unroll
        for (int off = 16; off; off >>= 1)
            s += __shfl_xor_sync(0xffffffffu, s, off);
        if (lane == 0) s_logden[il] = m + __logf(s);
    }
    __syncthreads();

    // ---- log_num -> R2 in place ----
    #pragma unroll
    for (int idx = t; idx < KL * OO; idx += 512) {
        const int kl = idx >> 5, oo = idx & 31;
        const int il = kl & 3, khw = kl >> 2;
        const int kg = khw * 32 + 4 * q + il;
        (void)oo;
        s_ln[idx] = fmaf(s_a8[kg], __expf(s_ln[idx] - s_logden[il]),
                         0.2f * s_R1[kg]);
    }
    __syncthreads();

    // ---- Pass C (M-step 2): sums of R2, R2*V, R2*V^2 from SMEM ----
    float cr = 0.f, crv = 0.f, crv2 = 0.f;
    {
        #pragma unroll 12
        for (int kl = 0; kl < KL; ++kl) {
            float v  = s_V[kl * 512 + c];
            float r  = s_ln[kl * OO + o];
            float rv = r * v;
            cr  += r;
            crv += rv;
            crv2 = fmaf(rv, v, crv2);
        }
        s_pC[c] = cr;
        s_pC[512 + c] = crv;
        s_pC[1024 + c] = crv2;
    }
    __syncthreads();
    cluster_sync();

    // ---- reduce pass C across CTAs; owner writes its output slice ----
    if (t < 64) {
        const int cp = 64 * q + t;
        const int op = cp >> 4, ap = cp & 15;
        const uint32_t pc = smem_u32(s_pC) + cp * 4;
        float scr = 0.f, scrv = 0.f, scrv2 = 0.f;
        #pragma unroll
        for (int r = 0; r < CL; ++r) {
            uint32_t ra = mapa_rank(pc, r);
            scr   += ld_dsmem(ra);
            scrv  += ld_dsmem(ra + 2048);
            scrv2 += ld_dsmem(ra + 4096);
        }
        const float invR = 1.0f / (scr + EPSC);
        const float mu2  = scrv * invR;
        out[pos * 512 + cp] = mu2;                              // poses

        const float sig2 = fmaf(mu2 * mu2, scr,
                                fmaf(-2.0f * mu2, scrv, scrv2)) * invR;
        float cost2 = (beta_u[op] - 0.5f * __logf(sig2 + EPSC)) * scr;
        #pragma unroll
        for (int off = 8; off; off >>= 1)
            cost2 += __shfl_xor_sync(0xffffffffu, cost2, off);
        if (ap == 0) {
            float arg = INVT2 * (beta_a[op] - cost2);
            out[NPOS * 512 + pos * OO + op] = 1.0f / (1.0f + __expf(-arg));
        }
    }

    cluster_sync();   // peers may still read our SMEM; no early exit
}

extern "C" void kernel_launch(void* const* d_in, const int* in_sizes, int n_in,
                              void* d_out, int out_size) {
    const float* votes  = (const float*)d_in[0];
    const float* activ  = (const float*)d_in[1];
    const float* beta_a = (const float*)d_in[2];
    const float* beta_u = (const float*)d_in[3];

    cudaFuncSetAttribute(em_routing_kernel,
                         cudaFuncAttributeMaxDynamicSharedMemorySize,
                         SMEM_BYTES);

    em_routing_kernel<<<NPOS * CL, 512, SMEM_BYTES>>>(
        votes, activ, beta_a, beta_u, (float*)d_out);
}

// round 4
// speedup vs baseline: 1.9358x; 1.9358x over previous
#include <cuda_runtime.h>
#include <math_constants.h>
#include <cstdint>

// Problem: votes (16,6,6,3,3,32,32,4,4); EM routing, 2 iterations.
#define NPOS   576            // B*H*W
#define KHW    9
#define II     32
#define OO     32
#define KDIM   (KHW*II)       // 288
#define PERPOS (KDIM*512)     // floats per position
#define EPSC   1e-7f
#define INVT1  0.0005f        // 0.01*(1-0.95^1)
#define INVT2  0.00142625f    // 0.01*(1-0.95^3)

#define SL     8              // k-slices for passes A/C
#define KSL    (KDIM/SL)      // 36 k per slice

// smem layout (floats)
#define OFF_R1    0                   // 288
#define OFF_A8    288                 // 288
#define OFF_Q2T   576                 // 512  [aa][o]
#define OFF_MQ1T  1088                // 512  [aa][o]
#define OFF_BASE  1600                // 32
#define OFF_S1    1632                // 8
#define OFF_LN    1640                // 9216  (becomes R2)
#define OFF_P     10856               // 8192  (slice partials, reused A then C)
#define OFF_PCR   19048               // 256   (pass C cr partials)
#define SMEM_REQ_BYTES (120*1024)     // pad: force 1 CTA/SM (L2 residency)

extern __shared__ float smem[];

__global__ __launch_bounds__(1024, 1)
void em_routing_kernel(const float* __restrict__ votes,
                       const float* __restrict__ activ,
                       const float* __restrict__ beta_a,
                       const float* __restrict__ beta_u,
                       float* __restrict__ out)
{
    float* s_R1   = smem + OFF_R1;
    float* s_a8   = smem + OFF_A8;
    float* s_q2T  = smem + OFF_Q2T;
    float* s_mq1T = smem + OFF_MQ1T;
    float* s_base = smem + OFF_BASE;
    float* s_S1   = smem + OFF_S1;
    float* s_ln   = smem + OFF_LN;
    float* s_p    = smem + OFF_P;
    float* s_pCr  = smem + OFF_PCR;

    const int t   = threadIdx.x;           // 0..1023
    const int pos = blockIdx.x;
    const float* __restrict__ V  = votes + (int64_t)pos * PERPOS;
    const float* __restrict__ Ai = activ + pos * KDIM;

    // ---- prologue ----
    if (t < KDIM) {
        float a = Ai[t];
        s_a8[t] = 0.8f * a;
        s_R1[t] = (0.8f * a + 0.2f) * (1.0f / 32.0f);
    }
    __syncthreads();
    if (t < 32) {
        float s = 0.f;
        #pragma unroll
        for (int k = t; k < KDIM; k += 32) s += s_R1[k];
        #pragma unroll
        for (int off = 16; off; off >>= 1) s += __shfl_xor_sync(0xffffffffu, s, off);
        if (t == 0) s_S1[0] = s;
    }

    const int sl = t >> 7;        // slice 0..7
    const int c4 = t & 127;       // float4 column group
    const int c0 = c4 * 4;        // first of 4 owned columns

    // ---- Pass A: slice sums of R1*V, R1*V^2 (float4) ----
    {
        const float4* gv = (const float4*)(V + (size_t)(sl * KSL) * 512 + c0);
        float4 av  = {0.f, 0.f, 0.f, 0.f};
        float4 av2 = {0.f, 0.f, 0.f, 0.f};
        #pragma unroll 6
        for (int k = 0; k < KSL; ++k) {
            float4 v = gv[k * 128];
            float  r = s_R1[sl * KSL + k];
            float rx = r * v.x, ry = r * v.y, rz = r * v.z, rw = r * v.w;
            av.x += rx; av.y += ry; av.z += rz; av.w += rw;
            av2.x = fmaf(rx, v.x, av2.x);
            av2.y = fmaf(ry, v.y, av2.y);
            av2.z = fmaf(rz, v.z, av2.z);
            av2.w = fmaf(rw, v.w, av2.w);
        }
        *(float4*)(s_p + sl * 1024 + c0)       = av;
        *(float4*)(s_p + sl * 1024 + 512 + c0) = av2;
    }
    __syncthreads();

    // ---- stats (M-step 1 closure): mu1/sigma1 tables + per-o base ----
    if (t < 512) {
        float av = 0.f, av2 = 0.f;
        #pragma unroll
        for (int ss = 0; ss < SL; ++ss) {
            av  += s_p[ss * 1024 + t];
            av2 += s_p[ss * 1024 + 512 + t];
        }
        const int   o     = t >> 4;
        const int   aa    = t & 15;
        const float S1    = s_S1[0];
        const float invS1 = 1.0f / (S1 + EPSC);
        const float mu1   = av * invS1;
        const float sig1  = fmaf(mu1 * mu1, S1, fmaf(-2.0f * mu1, av, av2)) * invS1;
        const float i2s1  = 0.5f / sig1;          // 1/(2 sigma^2), no eps (ref)
        const float q1    = mu1 * i2s1;
        s_q2T [aa * 32 + o] = i2s1;
        s_mq1T[aa * 32 + o] = -2.0f * q1;

        float Co   = mu1 * q1;
        float cc0  = __logf(fmaf(2.0f * CUDART_PI_F, sig1, EPSC));
        float cost = (beta_u[o] - 0.5f * __logf(sig1 + EPSC)) * S1;
        #pragma unroll
        for (int off = 8; off; off >>= 1) {
            Co   += __shfl_xor_sync(0xffffffffu, Co,   off);
            cc0  += __shfl_xor_sync(0xffffffffu, cc0,  off);
            cost += __shfl_xor_sync(0xffffffffu, cost, off);
        }
        if (aa == 0) {
            float arg = INVT1 * (beta_a[o] - cost);
            float aj  = 1.0f / (1.0f + __expf(-arg));
            s_base[o] = __logf(aj + EPSC) - cc0 - Co;
        }
    }
    __syncthreads();

    // ---- Pass B: warp w = i; lane = o. Warp-local E-step + R2 write ----
    {
        const int w = t >> 5;       // i
        const int o = t & 31;
        float q2r[16], mqr[16];
        #pragma unroll
        for (int a = 0; a < 16; ++a) {
            q2r[a] = s_q2T [a * 32 + o];
            mqr[a] = s_mq1T[a * 32 + o];
        }
        const float base = s_base[o];

        float x[KHW];
        #pragma unroll 3
        for (int j = 0; j < KHW; ++j) {
            const float4* pv = (const float4*)(V + (size_t)(j * 32 + w) * 512 + o * 16);
            float term = 0.f;
            #pragma unroll
            for (int g = 0; g < 4; ++g) {
                float4 v = pv[g];
                term = fmaf(v.x, fmaf(v.x, q2r[4*g+0], mqr[4*g+0]), term);
                term = fmaf(v.y, fmaf(v.y, q2r[4*g+1], mqr[4*g+1]), term);
                term = fmaf(v.z, fmaf(v.z, q2r[4*g+2], mqr[4*g+2]), term);
                term = fmaf(v.w, fmaf(v.w, q2r[4*g+3], mqr[4*g+3]), term);
            }
            x[j] = base - term;
        }
        // warp-local logsumexp over (khw, o)
        float m = x[0];
        #pragma unroll
        for (int j = 1; j < KHW; ++j) m = fmaxf(m, x[j]);
        #pragma unroll
        for (int off = 16; off; off >>= 1)
            m = fmaxf(m, __shfl_xor_sync(0xffffffffu, m, off));
        float s = 0.f;
        #pragma unroll
        for (int j = 0; j < KHW; ++j) s += __expf(x[j] - m);
        #pragma unroll
        for (int off = 16; off; off >>= 1)
            s += __shfl_xor_sync(0xffffffffu, s, off);
        const float logden = m + __logf(s);

        // R2 directly into s_ln
        #pragma unroll
        for (int j = 0; j < KHW; ++j) {
            const int k = j * 32 + w;
            s_ln[k * OO + o] = fmaf(s_a8[k], __expf(x[j] - logden), 0.2f * s_R1[k]);
        }
    }
    __syncthreads();

    // ---- Pass C: slice sums of R2, R2*V, R2*V^2 (float4) ----
    {
        const float4* gv = (const float4*)(V + (size_t)(sl * KSL) * 512 + c0);
        const int o = c4 >> 2;
        float4 crv  = {0.f, 0.f, 0.f, 0.f};
        float4 crv2 = {0.f, 0.f, 0.f, 0.f};
        float  cr   = 0.f;
        #pragma unroll 6
        for (int k = 0; k < KSL; ++k) {
            float4 v = gv[k * 128];
            float  r = s_ln[(sl * KSL + k) * OO + o];
            cr += r;
            float rx = r * v.x, ry = r * v.y, rz = r * v.z, rw = r * v.w;
            crv.x += rx; crv.y += ry; crv.z += rz; crv.w += rw;
            crv2.x = fmaf(rx, v.x, crv2.x);
            crv2.y = fmaf(ry, v.y, crv2.y);
            crv2.z = fmaf(rz, v.z, crv2.z);
            crv2.w = fmaf(rw, v.w, crv2.w);
        }
        *(float4*)(s_p + sl * 1024 + c0)       = crv;
        *(float4*)(s_p + sl * 1024 + 512 + c0) = crv2;
        if ((c4 & 3) == 0) s_pCr[sl * 32 + o] = cr;
    }
    __syncthreads();

    // ---- M-step 2 closure + outputs ----
    if (t < 512) {
        const int o = t >> 4;
        float cr = 0.f, crv = 0.f, crv2 = 0.f;
        #pragma unroll
        for (int ss = 0; ss < SL; ++ss) {
            crv  += s_p[ss * 1024 + t];
            crv2 += s_p[ss * 1024 + 512 + t];
            cr   += s_pCr[ss * 32 + o];
        }
        const float invR = 1.0f / (cr + EPSC);
        const float mu2  = crv * invR;
        out[pos * 512 + t] = mu2;                                // poses

        const float sig2 = fmaf(mu2 * mu2, cr, fmaf(-2.0f * mu2, crv, crv2)) * invR;
        float cost2 = (beta_u[o] - 0.5f * __logf(sig2 + EPSC)) * cr;
        #pragma unroll
        for (int off = 8; off; off >>= 1)
            cost2 += __shfl_xor_sync(0xffffffffu, cost2, off);
        if ((t & 15) == 0) {
            float arg = INVT2 * (beta_a[o] - cost2);
            out[NPOS * 512 + pos * OO + o] = 1.0f / (1.0f + __expf(-arg)); // acts
        }
    }
}

extern "C" void kernel_launch(void* const* d_in, const int* in_sizes, int n_in,
                              void* d_out, int out_size) {
    const float* votes  = (const float*)d_in[0];
    const float* activ  = (const float*)d_in[1];
    const float* beta_a = (const float*)d_in[2];
    const float* beta_u = (const float*)d_in[3];

    cudaFuncSetAttribute(em_routing_kernel,
                         cudaFuncAttributeMaxDynamicSharedMemorySize,
                         SMEM_REQ_BYTES);

    em_routing_kernel<<<NPOS, 1024, SMEM_REQ_BYTES>>>(
        votes, activ, beta_a, beta_u, (float*)d_out);
}

// round 5
// speedup vs baseline: 1.9579x; 1.0114x over previous
#include <cuda_runtime.h>
#include <math_constants.h>
#include <cstdint>

#define NPOS   576
#define KHW    9
#define II     32
#define OO     32
#define KDIM   (KHW*II)
#define PERPOS (KDIM*512)
#define EPSC   1e-7f
#define INVT1  0.0005f
#define INVT2  0.00142625f

#define SL     8
#define KSL    (KDIM/SL)

#define OFF_R1    0
#define OFF_A8    288
#define OFF_Q2T   576
#define OFF_MQ1T  1088
#define OFF_BASE  1600
#define OFF_S1    1632
#define OFF_LN    1640
#define OFF_P     10856
#define OFF_PCR   19048
#define SMEM_REQ_BYTES (120*1024)

extern __shared__ float smem[];

__device__ __forceinline__ uint64_t pk2(float lo, float hi) {
    uint64_t r; asm("mov.b64 %0, {%1, %2};" : "=l"(r) : "f"(lo), "f"(hi)); return r;
}
__device__ __forceinline__ void upk2(uint64_t p, float& lo, float& hi) {
    asm("mov.b64 {%0, %1}, %2;" : "=f"(lo), "=f"(hi) : "l"(p));
}
__device__ __forceinline__ uint64_t mul2(uint64_t a, uint64_t b) {
    uint64_t r; asm("mul.rn.f32x2 %0, %1, %2;" : "=l"(r) : "l"(a), "l"(b)); return r;
}
__device__ __forceinline__ uint64_t add2(uint64_t a, uint64_t b) {
    uint64_t r; asm("add.rn.f32x2 %0, %1, %2;" : "=l"(r) : "l"(a), "l"(b)); return r;
}
__device__ __forceinline__ uint64_t fma2(uint64_t a, uint64_t b, uint64_t c) {
    uint64_t r; asm("fma.rn.f32x2 %0, %1, %2, %3;" : "=l"(r) : "l"(a), "l"(b), "l"(c)); return r;
}

__global__ __launch_bounds__(1024, 1)
void em_routing_kernel(const float* __restrict__ votes,
                       const float* __restrict__ activ,
                       const float* __restrict__ beta_a,
                       const float* __restrict__ beta_u,
                       float* __restrict__ out)
{
    float* s_R1   = smem + OFF_R1;
    float* s_a8   = smem + OFF_A8;
    float* s_q2T  = smem + OFF_Q2T;
    float* s_mq1T = smem + OFF_MQ1T;
    float* s_base = smem + OFF_BASE;
    float* s_S1   = smem + OFF_S1;
    float* s_ln   = smem + OFF_LN;
    float* s_p    = smem + OFF_P;
    float* s_pCr  = smem + OFF_PCR;

    const int t   = threadIdx.x;
    const int pos = blockIdx.x;
    const float* __restrict__ V  = votes + (int64_t)pos * PERPOS;
    const float* __restrict__ Ai = activ + pos * KDIM;

    if (t < KDIM) {
        float a = Ai[t];
        s_a8[t] = 0.8f * a;
        s_R1[t] = (0.8f * a + 0.2f) * (1.0f / 32.0f);
    }
    __syncthreads();
    if (t < 32) {
        float s = 0.f;
        #pragma unroll
        for (int k = t; k < KDIM; k += 32) s += s_R1[k];
        #pragma unroll
        for (int off = 16; off; off >>= 1) s += __shfl_xor_sync(0xffffffffu, s, off);
        if (t == 0) s_S1[0] = s;
    }

    const int sl = t >> 7;
    const int c4 = t & 127;
    const int c0 = c4 * 4;

    // ---- Pass A ----
    {
        const ulonglong2* gv = (const ulonglong2*)(V + (size_t)(sl * KSL) * 512 + c0);
        uint64_t av0 = 0, av1 = 0, av20 = 0, av21 = 0;
        #pragma unroll 6
        for (int k = 0; k < KSL; ++k) {
            ulonglong2 v = gv[k * 128];
            float r = s_R1[sl * KSL + k];
            uint64_t r2  = pk2(r, r);
            uint64_t rv0 = mul2(r2, v.x);
            uint64_t rv1 = mul2(r2, v.y);
            av0  = add2(av0, rv0);
            av1  = add2(av1, rv1);
            av20 = fma2(rv0, v.x, av20);
            av21 = fma2(rv1, v.y, av21);
        }
        ulonglong2 st;
        st.x = av0;  st.y = av1;
        *(ulonglong2*)(s_p + sl * 1024 + c0) = st;
        st.x = av20; st.y = av21;
        *(ulonglong2*)(s_p + sl * 1024 + 512 + c0) = st;
    }
    __syncthreads();

    // ---- stats closure ----
    if (t < 512) {
        float av = 0.f, av2 = 0.f;
        #pragma unroll
        for (int ss = 0; ss < SL; ++ss) {
            av  += s_p[ss * 1024 + t];
            av2 += s_p[ss * 1024 + 512 + t];
        }
        const int   o     = t >> 4;
        const int   aa    = t & 15;
        const float S1    = s_S1[0];
        const float invS1 = 1.0f / (S1 + EPSC);
        const float mu1   = av * invS1;
        const float sig1  = fmaf(mu1 * mu1, S1, fmaf(-2.0f * mu1, av, av2)) * invS1;
        const float i2s1  = 0.5f / sig1;
        const float q1    = mu1 * i2s1;
        s_q2T [aa * 32 + o] = i2s1;
        s_mq1T[aa * 32 + o] = -2.0f * q1;

        float Co   = mu1 * q1;
        float cc0  = __logf(fmaf(2.0f * CUDART_PI_F, sig1, EPSC));
        float cost = (beta_u[o] - 0.5f * __logf(sig1 + EPSC)) * S1;
        #pragma unroll
        for (int off = 8; off; off >>= 1) {
            Co   += __shfl_xor_sync(0xffffffffu, Co,   off);
            cc0  += __shfl_xor_sync(0xffffffffu, cc0,  off);
            cost += __shfl_xor_sync(0xffffffffu, cost, off);
        }
        if (aa == 0) {
            float arg = INVT1 * (beta_a[o] - cost);
            float aj  = 1.0f / (1.0f + __expf(-arg));
            s_base[o] = __logf(aj + EPSC) - cc0 - Co;
        }
    }
    __syncthreads();

    // ---- Pass B ----
    {
        const int w = t >> 5;
        const int o = t & 31;
        uint64_t q2p[8], mqp[8];
        #pragma unroll
        for (int p = 0; p < 8; ++p) {
            q2p[p] = pk2(s_q2T [(2*p) * 32 + o], s_q2T [(2*p+1) * 32 + o]);
            mqp[p] = pk2(s_mq1T[(2*p) * 32 + o], s_mq1T[(2*p+1) * 32 + o]);
        }
        const float base = s_base[o];

        float x[KHW];
        #pragma unroll 3
        for (int j = 0; j < KHW; ++j) {
            const ulonglong2* pv =
                (const ulonglong2*)(V + (size_t)(j * 32 + w) * 512 + o * 16);
            ulonglong2 va = pv[0];   // aa 0..3   -> pairs 0,1
            ulonglong2 vb = pv[1];   // aa 4..7   -> pairs 2,3
            ulonglong2 vc = pv[2];   // aa 8..11  -> pairs 4,5
            ulonglong2 vd = pv[3];   // aa 12..15 -> pairs 6,7
            uint64_t t2 = 0;
            t2 = fma2(va.x, fma2(va.x, q2p[0], mqp[0]), t2);
            t2 = fma2(va.y, fma2(va.y, q2p[1], mqp[1]), t2);
            t2 = fma2(vb.x, fma2(vb.x, q2p[2], mqp[2]), t2);
            t2 = fma2(vb.y, fma2(vb.y, q2p[3], mqp[3]), t2);
            t2 = fma2(vc.x, fma2(vc.x, q2p[4], mqp[4]), t2);
            t2 = fma2(vc.y, fma2(vc.y, q2p[5], mqp[5]), t2);
            t2 = fma2(vd.x, fma2(vd.x, q2p[6], mqp[6]), t2);
            t2 = fma2(vd.y, fma2(vd.y, q2p[7], mqp[7]), t2);
            float tlo, thi;
            upk2(t2, tlo, thi);
            x[j] = base - (tlo + thi);
        }
        float m = x[0];
        #pragma unroll
        for (int j = 1; j < KHW; ++j) m = fmaxf(m, x[j]);
        #pragma unroll
        for (int off = 16; off; off >>= 1)
            m = fmaxf(m, __shfl_xor_sync(0xffffffffu, m, off));
        float s = 0.f;
        #pragma unroll
        for (int j = 0; j < KHW; ++j) { x[j] = __expf(x[j] - m); s += x[j]; }
        #pragma unroll
        for (int off = 16; off; off >>= 1)
            s += __shfl_xor_sync(0xffffffffu, s, off);
        const float invs = 1.0f / s;

        #pragma unroll
        for (int j = 0; j < KHW; ++j) {
            const int k = j * 32 + w;
            s_ln[k * OO + o] = fmaf(s_a8[k] * invs, x[j], 0.2f * s_R1[k]);
        }
    }
    __syncthreads();

    // ---- Pass C ----
    {
        const ulonglong2* gv = (const ulonglong2*)(V + (size_t)(sl * KSL) * 512 + c0);
        const int o = c4 >> 2;
        uint64_t crv0 = 0, crv1 = 0, crv20 = 0, crv21 = 0;
        float cr = 0.f;
        #pragma unroll 6
        for (int k = 0; k < KSL; ++k) {
            ulonglong2 v = gv[k * 128];
            float r = s_ln[(sl * KSL + k) * OO + o];
            cr += r;
            uint64_t r2  = pk2(r, r);
            uint64_t rv0 = mul2(r2, v.x);
            uint64_t rv1 = mul2(r2, v.y);
            crv0  = add2(crv0, rv0);
            crv1  = add2(crv1, rv1);
            crv20 = fma2(rv0, v.x, crv20);
            crv21 = fma2(rv1, v.y, crv21);
        }
        ulonglong2 st;
        st.x = crv0;  st.y = crv1;
        *(ulonglong2*)(s_p + sl * 1024 + c0) = st;
        st.x = crv20; st.y = crv21;
        *(ulonglong2*)(s_p + sl * 1024 + 512 + c0) = st;
        if ((c4 & 3) == 0) s_pCr[sl * 32 + o] = cr;
    }
    __syncthreads();

    // ---- final closure ----
    if (t < 512) {
        const int o = t >> 4;
        float cr = 0.f, crv = 0.f, crv2 = 0.f;
        #pragma unroll
        for (int ss = 0; ss < SL; ++ss) {
            crv  += s_p[ss * 1024 + t];
            crv2 += s_p[ss * 1024 + 512 + t];
            cr   += s_pCr[ss * 32 + o];
        }
        const float invR = 1.0f / (cr + EPSC);
        const float mu2  = crv * invR;
        out[pos * 512 + t] = mu2;

        const float sig2 = fmaf(mu2 * mu2, cr, fmaf(-2.0f * mu2, crv, crv2)) * invR;
        float cost2 = (beta_u[o] - 0.5f * __logf(sig2 + EPSC)) * cr;
        #pragma unroll
        for (int off = 8; off; off >>= 1)
            cost2 += __shfl_xor_sync(0xffffffffu, cost2, off);
        if ((t & 15) == 0) {
            float arg = INVT2 * (beta_a[o] - cost2);
            out[NPOS * 512 + pos * OO + o] = 1.0f / (1.0f + __expf(-arg));
        }
    }
}

extern "C" void kernel_launch(void* const* d_in, const int* in_sizes, int n_in,
                              void* d_out, int out_size) {
    const float* votes  = (const float*)d_in[0];
    const float* activ  = (const float*)d_in[1];
    const float* beta_a = (const float*)d_in[2];
    const float* beta_u = (const float*)d_in[3];

    cudaFuncSetAttribute(em_routing_kernel,
                         cudaFuncAttributeMaxDynamicSharedMemorySize,
                         SMEM_REQ_BYTES);

    em_routing_kernel<<<NPOS, 1024, SMEM_REQ_BYTES>>>(
        votes, activ, beta_a, beta_u, (float*)d_out);
}

// round 6
// speedup vs baseline: 2.0475x; 1.0458x over previous
#include <cuda_runtime.h>
#include <math_constants.h>
#include <cstdint>

// Problem: votes (16,6,6,3,3,32,32,4,4); EM routing, 2 iterations.
#define NPOS   576
#define KHW    9
#define OO     32
#define KDIM   288            // KH*KW*I
#define PERPOS (KDIM*512)
#define EPSC   1e-7f
#define INVT1  0.0005f        // 0.01*(1-0.95^1)
#define INVT2  0.00142625f    // 0.01*(1-0.95^3)

#define NT     512
#define SL     4
#define KSL    (KDIM/SL)      // 72

// smem layout (floats). s_G doubles as pass-A partial buffer (4096 < 8704).
#define OFF_G     0            // 16*544 = 8704  (per-warp crv partials, [w][o*17+aa])
#define OFF_G2    8704         // 8704           (per-warp crv2 partials)
#define OFF_R1    17408        // 288
#define OFF_A8    17696       // 288
#define OFF_Q2T   17984       // 528  [aa*33+o] = 1/(2*sigma1)
#define OFF_MQ1T  18512       // 528  [aa*33+o] = -2*mu1/(2*sigma1)
#define OFF_BASE  19040       // 32
#define OFF_S1    19072       // 8
#define OFF_AV    19080       // 544  [o*17+aa] pass-A sum R1*V
#define OFF_AV2   19624       // 544  [o*17+aa] pass-A sum R1*V^2
#define OFF_GR    20168       // 512  [w*32+o] per-warp cr partials
#define SMEM_REQ_BYTES (120*1024)   // force 1 CTA/SM -> 85MB working set L2-resident

extern __shared__ float smem[];

__device__ __forceinline__ uint64_t pk2(float lo, float hi) {
    uint64_t r; asm("mov.b64 %0, {%1, %2};" : "=l"(r) : "f"(lo), "f"(hi)); return r;
}
__device__ __forceinline__ void upk2(uint64_t p, float& lo, float& hi) {
    asm("mov.b64 {%0, %1}, %2;" : "=f"(lo), "=f"(hi) : "l"(p));
}
__device__ __forceinline__ uint64_t mul2(uint64_t a, uint64_t b) {
    uint64_t r; asm("mul.rn.f32x2 %0, %1, %2;" : "=l"(r) : "l"(a), "l"(b)); return r;
}
__device__ __forceinline__ uint64_t add2(uint64_t a, uint64_t b) {
    uint64_t r; asm("add.rn.f32x2 %0, %1, %2;" : "=l"(r) : "l"(a), "l"(b)); return r;
}
__device__ __forceinline__ uint64_t fma2(uint64_t a, uint64_t b, uint64_t c) {
    uint64_t r; asm("fma.rn.f32x2 %0, %1, %2, %3;" : "=l"(r) : "l"(a), "l"(b), "l"(c)); return r;
}

__global__ __launch_bounds__(NT, 1)
void em_routing_kernel(const float* __restrict__ votes,
                       const float* __restrict__ activ,
                       const float* __restrict__ beta_a,
                       const float* __restrict__ beta_u,
                       float* __restrict__ out)
{
    float* s_G    = smem + OFF_G;
    float* s_G2   = smem + OFF_G2;
    float* s_R1   = smem + OFF_R1;
    float* s_a8   = smem + OFF_A8;
    float* s_q2T  = smem + OFF_Q2T;
    float* s_mq1T = smem + OFF_MQ1T;
    float* s_base = smem + OFF_BASE;
    float* s_S1   = smem + OFF_S1;
    float* s_av   = smem + OFF_AV;
    float* s_av2  = smem + OFF_AV2;
    float* s_gr   = smem + OFF_GR;
    float* s_pA   = s_G;                 // pass-A partials alias (4*1024 floats)

    const int t   = threadIdx.x;         // 0..511
    const int pos = blockIdx.x;
    const float* __restrict__ V  = votes + (int64_t)pos * PERPOS;
    const float* __restrict__ Ai = activ + pos * KDIM;

    // ---- prologue ----
    if (t < KDIM) {
        float a = Ai[t];
        s_a8[t] = 0.8f * a;
        s_R1[t] = (0.8f * a + 0.2f) * (1.0f / 32.0f);
    }
    __syncthreads();
    if (t < 32) {
        float s = 0.f;
        #pragma unroll
        for (int k = t; k < KDIM; k += 32) s += s_R1[k];
        #pragma unroll
        for (int off = 16; off; off >>= 1) s += __shfl_xor_sync(0xffffffffu, s, off);
        if (t == 0) s_S1[0] = s;
    }

    // ---- Pass A: slice sums of R1*V, R1*V^2 (f32x2) ----
    {
        const int sl = t >> 7;           // 0..3
        const int c0 = (t & 127) * 4;
        const ulonglong2* gv = (const ulonglong2*)(V + (size_t)(sl * KSL) * 512 + c0);
        uint64_t av0 = 0, av1 = 0, av20 = 0, av21 = 0;
        #pragma unroll 8
        for (int k = 0; k < KSL; ++k) {
            ulonglong2 v = gv[k * 128];
            float r = s_R1[sl * KSL + k];
            uint64_t r2  = pk2(r, r);
            uint64_t rv0 = mul2(r2, v.x);
            uint64_t rv1 = mul2(r2, v.y);
            av0  = add2(av0, rv0);
            av1  = add2(av1, rv1);
            av20 = fma2(rv0, v.x, av20);
            av21 = fma2(rv1, v.y, av21);
        }
        ulonglong2 st;
        st.x = av0;  st.y = av1;
        *(ulonglong2*)(s_pA + sl * 1024 + c0) = st;
        st.x = av20; st.y = av21;
        *(ulonglong2*)(s_pA + sl * 1024 + 512 + c0) = st;
    }
    __syncthreads();

    // ---- stats closure: mu1/sigma1 tables, per-o base, stash av/av2 ----
    {
        float av = 0.f, av2 = 0.f;
        #pragma unroll
        for (int ss = 0; ss < SL; ++ss) {
            av  += s_pA[ss * 1024 + t];
            av2 += s_pA[ss * 1024 + 512 + t];
        }
        const int   o     = t >> 4;
        const int   aa    = t & 15;
        const float S1    = s_S1[0];
        const float invS1 = 1.0f / (S1 + EPSC);
        const float mu1   = av * invS1;
        const float sig1  = fmaf(mu1 * mu1, S1, fmaf(-2.0f * mu1, av, av2)) * invS1;
        const float i2s1  = 0.5f / sig1;           // 1/(2 sigma^2), no eps (ref)
        const float q1    = mu1 * i2s1;
        s_q2T [aa * 33 + o] = i2s1;
        s_mq1T[aa * 33 + o] = -2.0f * q1;
        s_av [o * 17 + aa] = av;
        s_av2[o * 17 + aa] = av2;

        float Co   = mu1 * q1;
        float cc0  = __logf(fmaf(2.0f * CUDART_PI_F, sig1, EPSC));
        float cost = (beta_u[o] - 0.5f * __logf(sig1 + EPSC)) * S1;
        #pragma unroll
        for (int off = 8; off; off >>= 1) {
            Co   += __shfl_xor_sync(0xffffffffu, Co,   off);
            cc0  += __shfl_xor_sync(0xffffffffu, cc0,  off);
            cost += __shfl_xor_sync(0xffffffffu, cost, off);
        }
        if (aa == 0) {
            float arg = INVT1 * (beta_a[o] - cost);
            float aj  = 1.0f / (1.0f + __expf(-arg));
            s_base[o] = __logf(aj + EPSC) - cc0 - Co;
        }
    }
    __syncthreads();   // also orders s_pA reads before pass B overwrites s_G

    // ---- Fused pass B+C: E-step + M-step-2 accumulation, single V read ----
    {
        const int w = t >> 5;            // warp 0..15
        const int o = t & 31;            // lane = output capsule
        uint64_t q2p[8], mqp[8];
        #pragma unroll
        for (int p = 0; p < 8; ++p) {
            q2p[p] = pk2(s_q2T [(2*p) * 33 + o], s_q2T [(2*p+1) * 33 + o]);
            mqp[p] = pk2(s_mq1T[(2*p) * 33 + o], s_mq1T[(2*p+1) * 33 + o]);
        }
        const float base = s_base[o];
        float* Gp  = s_G  + w * 544 + o * 17;
        float* G2p = s_G2 + w * 544 + o * 17;

        #pragma unroll
        for (int half = 0; half < 2; ++half) {
            const int i = w + half * 16;      // this warp's input capsule
            uint64_t g[8], g2[8];
            #pragma unroll
            for (int p = 0; p < 8; ++p) { g[p] = 0; g2[p] = 0; }
            float gr = 0.f, se = 0.f;

            #pragma unroll 3
            for (int j = 0; j < KHW; ++j) {
                const ulonglong2* pv =
                    (const ulonglong2*)(V + (size_t)(j * 32 + i) * 512 + o * 16);
                ulonglong2 va = pv[0];    // aa 0..3
                ulonglong2 vb = pv[1];    // aa 4..7
                ulonglong2 vc = pv[2];    // aa 8..11
                ulonglong2 vd = pv[3];    // aa 12..15
                uint64_t t2 = 0;
                t2 = fma2(va.x, fma2(va.x, q2p[0], mqp[0]), t2);
                t2 = fma2(va.y, fma2(va.y, q2p[1], mqp[1]), t2);
                t2 = fma2(vb.x, fma2(vb.x, q2p[2], mqp[2]), t2);
                t2 = fma2(vb.y, fma2(vb.y, q2p[3], mqp[3]), t2);
                t2 = fma2(vc.x, fma2(vc.x, q2p[4], mqp[4]), t2);
                t2 = fma2(vc.y, fma2(vc.y, q2p[5], mqp[5]), t2);
                t2 = fma2(vd.x, fma2(vd.x, q2p[6], mqp[6]), t2);
                t2 = fma2(vd.y, fma2(vd.y, q2p[7], mqp[7]), t2);
                float tlo, thi;
                upk2(t2, tlo, thi);
                // x = log_num (un-normalized); exp stays in fp32 normal range
                float e  = __expf(base - (tlo + thi));
                se += e;
                float ep = s_a8[j * 32 + i] * e;
                gr += ep;
                uint64_t ep2 = pk2(ep, ep);
                uint64_t rv;
                rv = mul2(ep2, va.x); g[0] = add2(g[0], rv); g2[0] = fma2(rv, va.x, g2[0]);
                rv = mul2(ep2, va.y); g[1] = add2(g[1], rv); g2[1] = fma2(rv, va.y, g2[1]);
                rv = mul2(ep2, vb.x); g[2] = add2(g[2], rv); g2[2] = fma2(rv, vb.x, g2[2]);
                rv = mul2(ep2, vb.y); g[3] = add2(g[3], rv); g2[3] = fma2(rv, vb.y, g2[3]);
                rv = mul2(ep2, vc.x); g[4] = add2(g[4], rv); g2[4] = fma2(rv, vc.x, g2[4]);
                rv = mul2(ep2, vc.y); g[5] = add2(g[5], rv); g2[5] = fma2(rv, vc.y, g2[5]);
                rv = mul2(ep2, vd.x); g[6] = add2(g[6], rv); g2[6] = fma2(rv, vd.x, g2[6]);
                rv = mul2(ep2, vd.y); g[7] = add2(g[7], rv); g2[7] = fma2(rv, vd.y, g2[7]);
            }

            // s_i = sum over (khw, o) of e  (warp-local: lanes are o, j summed)
            float s = se;
            #pragma unroll
            for (int off = 16; off; off >>= 1)
                s += __shfl_xor_sync(0xffffffffu, s, off);
            const float invs = 1.0f / s;

            // scale by 1/s_i, accumulate per-warp partials in smem
            if (half == 0) {
                #pragma unroll
                for (int p = 0; p < 8; ++p) {
                    float lo, hi;
                    upk2(g[p],  lo, hi); Gp [2*p] = invs * lo; Gp [2*p+1] = invs * hi;
                    upk2(g2[p], lo, hi); G2p[2*p] = invs * lo; G2p[2*p+1] = invs * hi;
                }
                s_gr[w * 32 + o] = invs * gr;
            } else {
                #pragma unroll
                for (int p = 0; p < 8; ++p) {
                    float lo, hi;
                    upk2(g[p],  lo, hi);
                    Gp [2*p] += invs * lo; Gp [2*p+1] += invs * hi;
                    upk2(g2[p], lo, hi);
                    G2p[2*p] += invs * lo; G2p[2*p+1] += invs * hi;
                }
                s_gr[w * 32 + o] += invs * gr;
            }
        }
    }
    __syncthreads();

    // ---- final closure: combine warp partials + 0.2*(pass-A sums) ----
    {
        const int o   = t >> 4;
        const int aa  = t & 15;
        const int idx = o * 17 + aa;
        float crv  = 0.2f * s_av [idx];
        float crv2 = 0.2f * s_av2[idx];
        float cr   = 0.2f * s_S1[0];
        #pragma unroll
        for (int w = 0; w < 16; ++w) {
            crv  += s_G [w * 544 + idx];
            crv2 += s_G2[w * 544 + idx];
            cr   += s_gr[w * 32 + o];
        }
        const float invR = 1.0f / (cr + EPSC);
        const float mu2  = crv * invR;
        out[pos * 512 + t] = mu2;                                  // poses

        const float sig2 = fmaf(mu2 * mu2, cr, fmaf(-2.0f * mu2, crv, crv2)) * invR;
        float cost2 = (beta_u[o] - 0.5f * __logf(sig2 + EPSC)) * cr;
        #pragma unroll
        for (int off = 8; off; off >>= 1)
            cost2 += __shfl_xor_sync(0xffffffffu, cost2, off);
        if (aa == 0) {
            float arg = INVT2 * (beta_a[o] - cost2);
            out[NPOS * 512 + pos * OO + o] = 1.0f / (1.0f + __expf(-arg)); // acts
        }
    }
}

extern "C" void kernel_launch(void* const* d_in, const int* in_sizes, int n_in,
                              void* d_out, int out_size) {
    const float* votes  = (const float*)d_in[0];
    const float* activ  = (const float*)d_in[1];
    const float* beta_a = (const float*)d_in[2];
    const float* beta_u = (const float*)d_in[3];

    cudaFuncSetAttribute(em_routing_kernel,
                         cudaFuncAttributeMaxDynamicSharedMemorySize,
                         SMEM_REQ_BYTES);

    em_routing_kernel<<<NPOS, NT, SMEM_REQ_BYTES>>>(
        votes, activ, beta_a, beta_u, (float*)d_out);
}